// round 13
// baseline (speedup 1.0000x reference)
#include <cuda_runtime.h>
#include <math.h>
#include <float.h>

#define NMAX 50000
#define EMAX 400000

// Scratch (allocation-free rule: __device__ globals)
__device__ float g_u[NMAX * 128];
__device__ float g_v[NMAX * 128];
__device__ float g_aggr64[NMAX * 64];   // aggregated mol_x (64-wide)
__device__ float g_sp[NMAX];            // per-node sum of p
__device__ float g_s[EMAX];             // edge scores, then p=exp(s-max)
__device__ int   g_eid[EMAX];           // CSR edge ids
__device__ int   g_deg[NMAX];           // degree histogram
__device__ int   g_off[NMAX + 1];       // CSR offsets (mutated by fill)
__device__ int   g_bsum[64];            // scan block sums (raw totals)
__device__ unsigned int g_maxkey;
__device__ float g_sum;
// composite weights
__device__ float g_Wcu[64 * 128], g_Wcv[64 * 128], g_Wnu[64 * 128];
__device__ float g_bcu[128], g_bcv[128], g_bnu[128];
__device__ float g_W1y[64 * 64], g_b1y[64];
__device__ float g_W1a[64 * 64], g_b1a[64];

// --- monotonic float<->uint key for atomicMax over signed floats ---
__device__ __forceinline__ unsigned fkey(float f) {
    unsigned b = __float_as_uint(f);
    return (b & 0x80000000u) ? ~b : (b | 0x80000000u);
}
__device__ __forceinline__ float fdecode(unsigned k) {
    return __uint_as_float((k & 0x80000000u) ? (k ^ 0x80000000u) : ~k);
}

// ---------------------------------------------------------------------------
// init: zero degree histogram only (pure CSR-chain dependency)
// ---------------------------------------------------------------------------
__global__ void init_k(int N) {
    int i = blockIdx.x * blockDim.x + threadIdx.x;
    for (int j = i; j < N; j += gridDim.x * blockDim.x) g_deg[j] = 0;
}

// ---------------------------------------------------------------------------
// ONE kernel for all composite weights. g_bcu folds in b_att1.
// Thread 33280 also resets the softmax scalars (keeps edge_k's deps on the
// main stream only).
// ---------------------------------------------------------------------------
__global__ void compose_all_k(const float* __restrict__ Wn, const float* __restrict__ bn,
                              const float* __restrict__ Watt, const float* __restrict__ batt1,
                              const float* __restrict__ Wupd,
                              const float* __restrict__ Wy1, const float* __restrict__ by1,
                              const float* __restrict__ Wa1, const float* __restrict__ ba1) {
    int id = blockIdx.x * blockDim.x + threadIdx.x;
    if (id < 24576) {                     // three [64,128] composites
        int sel = id >> 13, k = id & 8191, f = k >> 7, j = k & 127;
        const float* B = (sel == 0) ? Watt : (sel == 1) ? (Watt + 128 * 128) : Wupd;
        float* O = (sel == 0) ? g_Wcu : (sel == 1) ? g_Wcv : g_Wnu;
        float a = 0.f;
        for (int m = 0; m < 128; m++) a += Wn[f * 128 + m] * B[m * 128 + j];
        O[k] = a;
    } else if (id < 32768) {              // two [64,64] head composites
        int k = id - 24576, sel = k >> 12, kk = k & 4095, f = kk >> 6, j = kk & 63;
        const float* B = sel ? Wa1 : Wy1;
        float* O = sel ? g_W1a : g_W1y;
        float a = 0.f;
        for (int m = 0; m < 128; m++) a += Wn[f * 128 + m] * B[m * 64 + j];
        O[kk] = a;
    } else if (id < 33152) {              // three [128] bias composites
        int k = id - 32768, sel = k >> 7, j = k & 127;
        const float* B = (sel == 0) ? Watt : (sel == 1) ? (Watt + 128 * 128) : Wupd;
        float* O = (sel == 0) ? g_bcu : (sel == 1) ? g_bcv : g_bnu;
        float a = (sel == 0) ? batt1[j] : 0.f;   // fold b_att1 into bcu
        for (int m = 0; m < 128; m++) a += bn[m] * B[m * 128 + j];
        O[j] = a;
    } else if (id < 33280) {              // two [64] head biases
        int k = id - 33152, sel = k >> 6, j = k & 63;
        const float* B = sel ? Wa1 : Wy1;
        float a = sel ? ba1[j] : by1[j];
        for (int m = 0; m < 128; m++) a += bn[m] * B[m * 64 + j];
        (sel ? g_b1a : g_b1y)[j] = a;
    } else if (id == 33280) {             // softmax scalar reset
        g_maxkey = 0u;
        g_sum = 0.f;
    }
}

// ---------------------------------------------------------------------------
// CSR build: histogram, scanA (per-1024-block exclusive + raw block totals),
// addoff (adds prefix of block totals in-kernel; replaces scanB)
// ---------------------------------------------------------------------------
__global__ void hist_k(const int* __restrict__ dst, int E) {
    for (int i = blockIdx.x * blockDim.x + threadIdx.x; i < E; i += gridDim.x * blockDim.x)
        atomicAdd(&g_deg[dst[i]], 1);
}

__global__ void scanA_k(int n) {
    __shared__ int wsum[32];
    int t = threadIdx.x, lane = t & 31, wid = t >> 5;
    int i = blockIdx.x * 1024 + t;
    int v = (i < n) ? g_deg[i] : 0;
    int x = v;
#pragma unroll
    for (int o = 1; o < 32; o <<= 1) {
        int y = __shfl_up_sync(0xffffffffu, x, o);
        if (lane >= o) x += y;
    }
    if (lane == 31) wsum[wid] = x;
    __syncthreads();
    if (wid == 0) {
        int w = wsum[lane];
#pragma unroll
        for (int o = 1; o < 32; o <<= 1) {
            int y = __shfl_up_sync(0xffffffffu, w, o);
            if (lane >= o) w += y;
        }
        wsum[lane] = w;
    }
    __syncthreads();
    int excl = (wid ? wsum[wid - 1] : 0) + x - v;
    if (i < n) g_off[i] = excl;
    if (t == 0) g_bsum[blockIdx.x] = wsum[31];
}

// addoff: g_off[i] += sum of raw block totals before block (i>>10).
// A 256-wide block spans at most 2 scan-block ids.
__global__ void addoff_k(int n) {
    __shared__ int pre[2];
    int base = blockIdx.x * 256;
    int sb0 = base >> 10;
    if (threadIdx.x < 2) {
        int sb = sb0 + threadIdx.x;
        int a = 0;
        for (int j = 0; j < sb; j++) a += g_bsum[j];
        pre[threadIdx.x] = a;
    }
    __syncthreads();
    int i = base + threadIdx.x;
    if (i < n) g_off[i] += pre[(i >> 10) - sb0];
}

// fill: p = exp(s-max) in place, accumulate g_sum, slot edges into CSR.
// atomicAdd on g_off itself: post-fill, g_off[d] == original g_off[d+1],
// so node d's range is [d ? g_off[d-1] : 0, g_off[d]).
__global__ void fill_k(const int* __restrict__ dst, int E) {
    float mx = fdecode(g_maxkey);
    float loc = 0.f;
    for (int i = blockIdx.x * blockDim.x + threadIdx.x; i < E; i += gridDim.x * blockDim.x) {
        float p = expf(g_s[i] - mx);
        g_s[i] = p;
        loc += p;
        int slot = atomicAdd(&g_off[dst[i]], 1);
        g_eid[slot] = i;
    }
    for (int o = 16; o; o >>= 1) loc += __shfl_xor_sync(0xffffffffu, loc, o);
    __shared__ float ws[8];
    int lane = threadIdx.x & 31, wid = threadIdx.x >> 5;
    if (lane == 0) ws[wid] = loc;
    __syncthreads();
    if (threadIdx.x == 0) {
        float tot = 0.f;
        for (int i = 0; i < (int)(blockDim.x >> 5); i++) tot += ws[i];
        atomicAdd(&g_sum, tot);
    }
}

// ---------------------------------------------------------------------------
// Encoder: u,v [n,128] from mol_x [n,64] via composite weights.
// ---------------------------------------------------------------------------
__global__ void __launch_bounds__(256)
enc_k(const float* __restrict__ X, int n) {
    extern __shared__ float sm[];
    float* Ws = sm;            // 2 * 8192
    float* bs = sm + 16384;    // 2 * 128
    float* Xs = bs + 256;      // 32 * 64
    int t = threadIdx.x;
    int col = t & 127, half = t >> 7;
    for (int i = t; i < 2048; i += 256) ((float4*)Ws)[i]          = ((const float4*)g_Wcu)[i];
    for (int i = t; i < 2048; i += 256) ((float4*)(Ws + 8192))[i] = ((const float4*)g_Wcv)[i];
    if (t < 128) { bs[t] = g_bcu[t]; bs[128 + t] = g_bcv[t]; }

    for (int row0 = blockIdx.x * 32; row0 < n; row0 += gridDim.x * 32) {
        int nr = min(32, n - row0);
        __syncthreads();
        for (int i = t; i < nr * 16; i += 256)
            ((float4*)Xs)[i] = ((const float4*)(X + (size_t)row0 * 64))[i];
        __syncthreads();

#pragma unroll 1
        for (int g = 0; g < 2; g++) {
            const float* Wg = Ws + g * 8192;
            float acc[16];
#pragma unroll
            for (int r = 0; r < 16; r++) acc[r] = 0.f;
            for (int k4 = 0; k4 < 64; k4 += 4) {
                float w0 = Wg[(k4 + 0) * 128 + col];
                float w1 = Wg[(k4 + 1) * 128 + col];
                float w2 = Wg[(k4 + 2) * 128 + col];
                float w3 = Wg[(k4 + 3) * 128 + col];
#pragma unroll
                for (int r = 0; r < 16; r++) {
                    float4 xv = *(const float4*)&Xs[(half * 16 + r) * 64 + k4];
                    acc[r] += xv.x * w0 + xv.y * w1 + xv.z * w2 + xv.w * w3;
                }
            }
            float bv = bs[g * 128 + col];
            float* O = g ? g_v : g_u;
            int rmax = min(16, nr - half * 16);
            for (int r = 0; r < rmax; r++)
                O[(size_t)(row0 + half * 16 + r) * 128 + col] = acc[r] + bv;
        }
    }
}

// ---------------------------------------------------------------------------
// Edge attention score + fused global max (persistent warps, 2-edge ILP,
// lane-split pos gather). b_att1 pre-folded into g_u.
// ---------------------------------------------------------------------------
__global__ void edge_k(const int* __restrict__ src, const int* __restrict__ dst,
                       const float* __restrict__ pos,
                       const float* __restrict__ Wd,
                       const float* __restrict__ W2, const float* __restrict__ b2,
                       int E) {
    int lane = threadIdx.x & 31;
    int wid = threadIdx.x >> 5;
    int gw = (blockIdx.x * blockDim.x + threadIdx.x) >> 5;
    int nw = (gridDim.x * blockDim.x) >> 5;

    float4 c0 = ((const float4*)Wd)[lane];
    float4 c1 = ((const float4*)(Wd + 128))[lane];
    float4 c2 = ((const float4*)(Wd + 256))[lane];
    float4 w2 = ((const float4*)W2)[lane];
    float b2v = b2[0];

    const unsigned FULL = 0xffffffffu;
    float wmax = -FLT_MAX;
    for (int e0 = gw * 2; e0 < E; e0 += 2 * nw) {
        int e1 = e0 + 1;
        bool has1 = e1 < E;                 // warp-uniform
        int e1c = has1 ? e1 : e0;           // clamped index (always valid)

        int sn0 = src[e0], dn0 = dst[e0];
        int sn1 = src[e1c], dn1 = dst[e1c];

        float4 a0 = ((const float4*)(g_u + (size_t)dn0 * 128))[lane];
        float4 j0 = ((const float4*)(g_v + (size_t)sn0 * 128))[lane];
        float4 a1 = ((const float4*)(g_u + (size_t)dn1 * 128))[lane];
        float4 j1 = ((const float4*)(g_v + (size_t)sn1 * 128))[lane];

        float pv = 0.f;
        if (lane < 12) {
            int sel = lane / 3, comp = lane - sel * 3;
            int node = (sel == 0) ? dn0 : (sel == 1) ? sn0 : (sel == 2) ? dn1 : sn1;
            pv = pos[node * 3 + comp];
        }
        float dx0 = __shfl_sync(FULL, pv, 0) - __shfl_sync(FULL, pv, 3);
        float dy0 = __shfl_sync(FULL, pv, 1) - __shfl_sync(FULL, pv, 4);
        float dz0 = __shfl_sync(FULL, pv, 2) - __shfl_sync(FULL, pv, 5);
        float dx1 = __shfl_sync(FULL, pv, 6) - __shfl_sync(FULL, pv, 9);
        float dy1 = __shfl_sync(FULL, pv, 7) - __shfl_sync(FULL, pv, 10);
        float dz1 = __shfl_sync(FULL, pv, 8) - __shfl_sync(FULL, pv, 11);

        float p0, p1;
        {
            float t0 = fmaxf(a0.x + j0.x + dx0 * c0.x + dy0 * c1.x + dz0 * c2.x, 0.f);
            float t1 = fmaxf(a0.y + j0.y + dx0 * c0.y + dy0 * c1.y + dz0 * c2.y, 0.f);
            float t2 = fmaxf(a0.z + j0.z + dx0 * c0.z + dy0 * c1.z + dz0 * c2.z, 0.f);
            float t3 = fmaxf(a0.w + j0.w + dx0 * c0.w + dy0 * c1.w + dz0 * c2.w, 0.f);
            p0 = t0 * w2.x + t1 * w2.y + t2 * w2.z + t3 * w2.w;
        }
        {
            float t0 = fmaxf(a1.x + j1.x + dx1 * c0.x + dy1 * c1.x + dz1 * c2.x, 0.f);
            float t1 = fmaxf(a1.y + j1.y + dx1 * c0.y + dy1 * c1.y + dz1 * c2.y, 0.f);
            float t2 = fmaxf(a1.z + j1.z + dx1 * c0.z + dy1 * c1.z + dz1 * c2.z, 0.f);
            float t3 = fmaxf(a1.w + j1.w + dx1 * c0.w + dy1 * c1.w + dz1 * c2.w, 0.f);
            p1 = t0 * w2.x + t1 * w2.y + t2 * w2.z + t3 * w2.w;
        }

#pragma unroll
        for (int o = 16; o; o >>= 1) {
            p0 += __shfl_xor_sync(FULL, p0, o);
            p1 += __shfl_xor_sync(FULL, p1, o);
        }
        float s0 = p0 + b2v;
        float s1 = p1 + b2v;
        if (lane == 0) g_s[e0] = s0;
        wmax = fmaxf(wmax, s0);
        if (has1) {
            if (lane == 0) g_s[e1] = s1;
            wmax = fmaxf(wmax, s1);
        }
    }

    __shared__ float wm[8];
    if (lane == 0) wm[wid] = wmax;
    __syncthreads();
    if (threadIdx.x == 0) {
        float m = wm[0];
        for (int i = 1; i < (int)(blockDim.x >> 5); i++) m = fmaxf(m, wm[i]);
        atomicMax(&g_maxkey, fkey(m));
    }
}

// ---------------------------------------------------------------------------
// Gather aggregation (atomic-free): HALF-WARP per node, register accumulate.
// ---------------------------------------------------------------------------
__global__ void gather_k(const int* __restrict__ src, const float* __restrict__ molx,
                         int N) {
    int node = (blockIdx.x * blockDim.x + threadIdx.x) >> 4;
    int l16 = threadIdx.x & 15;
    if (node >= N) return;
    int beg = node ? g_off[node - 1] : 0;
    int end = g_off[node];
    float4 acc = make_float4(0.f, 0.f, 0.f, 0.f);
    float sp = 0.f;
    for (int i = beg; i < end; i++) {
        int e = g_eid[i];
        float p = g_s[e];
        int sn = src[e];
        float4 x = ((const float4*)(molx + (size_t)sn * 64))[l16];
        acc.x += x.x * p; acc.y += x.y * p; acc.z += x.z * p; acc.w += x.w * p;
        sp += p;
    }
    ((float4*)(g_aggr64 + (size_t)node * 64))[l16] = acc;
    if (l16 == 0) g_sp[node] = sp;
}

// ---------------------------------------------------------------------------
// Final GEMM (K=64): mol_feats = (aggr64@Wnu + sp*bnu)/sum + b_upd
// ---------------------------------------------------------------------------
__global__ void __launch_bounds__(256)
final_k(const float* __restrict__ bupd, float* __restrict__ Y, int n) {
    extern __shared__ float sm[];
    float* Ws = sm;            // 8192
    float* bs = sm + 8192;     // 2*128 (bnu, bupd)
    float* Xs = bs + 256;      // 32*64
    int t = threadIdx.x;
    int col = t & 127, half = t >> 7;
    for (int i = t; i < 2048; i += 256) ((float4*)Ws)[i] = ((const float4*)g_Wnu)[i];
    if (t < 128) { bs[t] = g_bnu[t]; bs[128 + t] = bupd[t]; }

    float is = 1.f / g_sum;

    for (int row0 = blockIdx.x * 32; row0 < n; row0 += gridDim.x * 32) {
        int nr = min(32, n - row0);
        __syncthreads();
        for (int i = t; i < nr * 16; i += 256)
            ((float4*)Xs)[i] = ((const float4*)(g_aggr64 + (size_t)row0 * 64))[i];
        __syncthreads();

        float acc[16];
#pragma unroll
        for (int r = 0; r < 16; r++) acc[r] = 0.f;
        for (int k4 = 0; k4 < 64; k4 += 4) {
            float w0 = Ws[(k4 + 0) * 128 + col];
            float w1 = Ws[(k4 + 1) * 128 + col];
            float w2 = Ws[(k4 + 2) * 128 + col];
            float w3 = Ws[(k4 + 3) * 128 + col];
#pragma unroll
            for (int r = 0; r < 16; r++) {
                float4 xv = *(const float4*)&Xs[(half * 16 + r) * 64 + k4];
                acc[r] += xv.x * w0 + xv.y * w1 + xv.z * w2 + xv.w * w3;
            }
        }
        float bnuv = bs[col], bupv = bs[128 + col];
        int rmax = min(16, nr - half * 16);
        for (int r = 0; r < rmax; r++) {
            int row = row0 + half * 16 + r;
            float sp = g_sp[row];
            Y[(size_t)row * 128 + col] = (acc[r] + sp * bnuv) * is + bupv;
        }
    }
}

// ---------------------------------------------------------------------------
// BOTH heads in one launch. Block picks (y) or (a) params by blockIdx.
// ---------------------------------------------------------------------------
__global__ void heads_k(const float* __restrict__ Ry, const float* __restrict__ W2y,
                        const float* __restrict__ b2y, float* __restrict__ outY, int nY,
                        const float* __restrict__ Ra, const float* __restrict__ W2a,
                        const float* __restrict__ b2a, float* __restrict__ outA, int nA,
                        int blocksY) {
    __shared__ float W1s[64 * 64];
    __shared__ float b1s[64];
    __shared__ float W2s[64];
    __shared__ float rows[8][64];
    int t = threadIdx.x, lane = t & 31, wid = t >> 5;

    bool isY = blockIdx.x < blocksY;
    int bid = isY ? blockIdx.x : blockIdx.x - blocksY;
    const float* R   = isY ? Ry : Ra;
    const float* W1c = isY ? g_W1y : g_W1a;
    const float* b1c = isY ? g_b1y : g_b1a;
    const float* W2  = isY ? W2y : W2a;
    const float* b2  = isY ? b2y : b2a;
    float* out = isY ? outY : outA;
    int n = isY ? nY : nA;

    for (int i = t; i < 64 * 64; i += 256) W1s[i] = W1c[i];
    if (t < 64) { b1s[t] = b1c[t]; W2s[t] = W2[t]; }
    __syncthreads();
    float b2v = b2[0];
    int row = bid * 8 + wid;
    if (row < n) {
        if (lane < 16) ((float4*)rows[wid])[lane] = ((const float4*)(R + (size_t)row * 64))[lane];
        __syncwarp();
        float h0 = b1s[lane], h1 = b1s[lane + 32];
#pragma unroll 8
        for (int k = 0; k < 64; k++) {
            float x = rows[wid][k];
            h0 += x * W1s[k * 64 + lane];
            h1 += x * W1s[k * 64 + lane + 32];
        }
        float p = fmaxf(h0, 0.f) * W2s[lane] + fmaxf(h1, 0.f) * W2s[lane + 32];
        for (int o = 16; o; o >>= 1) p += __shfl_xor_sync(0xffffffffu, p, o);
        if (lane == 0) out[row] = p + b2v;
    }
}

// ---------------------------------------------------------------------------
extern "C" void kernel_launch(void* const* d_in, const int* in_sizes, int n_in,
                              void* d_out, int out_size) {
    const float* mol_x  = (const float*)d_in[0];
    const float* pos    = (const float*)d_in[1];
    const float* rx     = (const float*)d_in[2];
    const float* tx     = (const float*)d_in[3];
    const int*   ei     = (const int*)d_in[4];
    const float* W_node = (const float*)d_in[5];
    const float* b_node = (const float*)d_in[6];
    const float* W_att1 = (const float*)d_in[7];
    const float* b_att1 = (const float*)d_in[8];
    const float* W_att2 = (const float*)d_in[9];
    const float* b_att2 = (const float*)d_in[10];
    const float* W_upd  = (const float*)d_in[11];
    const float* b_upd  = (const float*)d_in[12];
    const float* Wy1 = (const float*)d_in[13];
    const float* by1 = (const float*)d_in[14];
    const float* Wy2 = (const float*)d_in[15];
    const float* by2 = (const float*)d_in[16];
    const float* Wa1 = (const float*)d_in[17];
    const float* ba1 = (const float*)d_in[18];
    const float* Wa2 = (const float*)d_in[19];
    const float* ba2 = (const float*)d_in[20];

    int N  = in_sizes[0] / 64;
    int NR = in_sizes[2] / 64;
    int NT = in_sizes[3] / 64;
    int E  = in_sizes[4] / 2;
    const int* srcP = ei;
    const int* dstP = ei + E;

    float* out   = (float*)d_out;
    float* out_y = out;             // pred_yield  [NR]
    float* out_a = out + NR;        // pred_activity [NT]
    float* out_m = out + NR + NT;   // mol_feats [N,128]

    int smem_enc   = (2 * 64 * 128 + 2 * 128 + 32 * 64) * 4;  // ~74 KB
    int smem_final = (64 * 128 + 2 * 128 + 32 * 64) * 4;      // ~42 KB
    cudaFuncSetAttribute(enc_k,   cudaFuncAttributeMaxDynamicSharedMemorySize, smem_enc);
    cudaFuncSetAttribute(final_k, cudaFuncAttributeMaxDynamicSharedMemorySize, smem_final);

    auto pgrid = [](int rows, int cap) {
        int tiles = (rows + 31) / 32;
        return tiles < cap ? tiles : cap;
    };

    // Side streams + events created once (during the uncaptured correctness
    // run); fork/join via events is graph-capture-legal.
    static cudaStream_t sCsr = nullptr, sHead = nullptr;
    static cudaEvent_t eFork, eCompose, eCsrDone, eHeadDone;
    if (!sCsr) {
        cudaStreamCreateWithFlags(&sCsr,  cudaStreamNonBlocking);
        cudaStreamCreateWithFlags(&sHead, cudaStreamNonBlocking);
        cudaEventCreateWithFlags(&eFork,     cudaEventDisableTiming);
        cudaEventCreateWithFlags(&eCompose,  cudaEventDisableTiming);
        cudaEventCreateWithFlags(&eCsrDone,  cudaEventDisableTiming);
        cudaEventCreateWithFlags(&eHeadDone, cudaEventDisableTiming);
    }

    // ---- fork CSR chain (depends only on dst) ----
    cudaEventRecord(eFork, 0);
    cudaStreamWaitEvent(sCsr, eFork, 0);
    init_k<<<64, 256, 0, sCsr>>>(N);
    hist_k<<<592, 256, 0, sCsr>>>(dstP, E);
    int nbScan = (N + 1023) / 1024;
    scanA_k<<<nbScan, 1024, 0, sCsr>>>(N);
    addoff_k<<<(N + 255) / 256, 256, 0, sCsr>>>(N);
    cudaEventRecord(eCsrDone, sCsr);

    // ---- main chain ----
    compose_all_k<<<131, 256>>>(W_node, b_node, W_att1, b_att1, W_upd,
                                Wy1, by1, Wa1, ba1);
    cudaEventRecord(eCompose, 0);

    // ---- fork heads (depend only on compose) ----
    cudaStreamWaitEvent(sHead, eCompose, 0);
    int blocksY = (NR + 7) / 8, blocksA = (NT + 7) / 8;
    heads_k<<<blocksY + blocksA, 256, 0, sHead>>>(rx, Wy2, by2, out_y, NR,
                                                  tx, Wa2, ba2, out_a, NT, blocksY);
    cudaEventRecord(eHeadDone, sHead);

    // u, v from mol_x via composite weights
    enc_k<<<pgrid(N, 2 * 148), 256, smem_enc>>>(mol_x, N);

    // per-edge score + fused global max
    edge_k<<<592, 256>>>(srcP, dstP, pos, W_att1 + 256 * 128, W_att2, b_att2, E);

    // join CSR chain, then exp + g_sum + CSR fill
    cudaStreamWaitEvent(0, eCsrDone, 0);
    fill_k<<<592, 256>>>(dstP, E);

    // atomic-free gather aggregation (also produces g_sp)
    gather_k<<<(N * 16 + 255) / 256, 256>>>(srcP, mol_x, N);

    // final K=64 GEMM -> mol_feats
    final_k<<<pgrid(N, 4 * 148), 256, smem_final>>>(b_upd, out_m, N);

    // join heads
    cudaStreamWaitEvent(0, eHeadDone, 0);
}

// round 14
// speedup vs baseline: 1.0924x; 1.0924x over previous
#include <cuda_runtime.h>
#include <math.h>
#include <float.h>

#define NMAX 50000
#define EMAX 400000

// Scratch (allocation-free rule: __device__ globals)
__device__ float g_u[NMAX * 128];
__device__ float g_v[NMAX * 128];
__device__ float g_aggr64[NMAX * 64];   // aggregated mol_x (64-wide)
__device__ float g_sp[NMAX];            // per-node sum of p
__device__ float g_s[EMAX];             // edge scores, then p=exp(s-max)
__device__ int   g_eid[EMAX];           // CSR edge ids
__device__ int   g_deg[NMAX];           // degree histogram
__device__ int   g_off[NMAX + 1];       // CSR offsets (mutated by fill)
__device__ int   g_bsum[64];            // scan block sums
__device__ unsigned int g_maxkey;
__device__ float g_sum;
// composite weights
__device__ float g_Wcu[64 * 128], g_Wcv[64 * 128], g_Wnu[64 * 128];
__device__ float g_bcu[128], g_bcv[128], g_bnu[128];
__device__ float g_W1y[64 * 64], g_b1y[64];
__device__ float g_W1a[64 * 64], g_b1a[64];

// --- monotonic float<->uint key for atomicMax over signed floats ---
__device__ __forceinline__ unsigned fkey(float f) {
    unsigned b = __float_as_uint(f);
    return (b & 0x80000000u) ? ~b : (b | 0x80000000u);
}
__device__ __forceinline__ float fdecode(unsigned k) {
    return __uint_as_float((k & 0x80000000u) ? (k ^ 0x80000000u) : ~k);
}

// ---------------------------------------------------------------------------
__global__ void init_k(int N) {
    int i = blockIdx.x * blockDim.x + threadIdx.x;
    if (i == 0) { g_maxkey = 0u; g_sum = 0.f; }
    for (int j = i; j < N; j += gridDim.x * blockDim.x) g_deg[j] = 0;
}

// ---------------------------------------------------------------------------
// ONE kernel for all composite weights. g_bcu folds in b_att1.
// ---------------------------------------------------------------------------
__global__ void compose_all_k(const float* __restrict__ Wn, const float* __restrict__ bn,
                              const float* __restrict__ Watt, const float* __restrict__ batt1,
                              const float* __restrict__ Wupd,
                              const float* __restrict__ Wy1, const float* __restrict__ by1,
                              const float* __restrict__ Wa1, const float* __restrict__ ba1) {
    int id = blockIdx.x * blockDim.x + threadIdx.x;
    if (id < 24576) {                     // three [64,128] composites
        int sel = id >> 13, k = id & 8191, f = k >> 7, j = k & 127;
        const float* B = (sel == 0) ? Watt : (sel == 1) ? (Watt + 128 * 128) : Wupd;
        float* O = (sel == 0) ? g_Wcu : (sel == 1) ? g_Wcv : g_Wnu;
        float a = 0.f;
        for (int m = 0; m < 128; m++) a += Wn[f * 128 + m] * B[m * 128 + j];
        O[k] = a;
    } else if (id < 32768) {              // two [64,64] head composites
        int k = id - 24576, sel = k >> 12, kk = k & 4095, f = kk >> 6, j = kk & 63;
        const float* B = sel ? Wa1 : Wy1;
        float* O = sel ? g_W1a : g_W1y;
        float a = 0.f;
        for (int m = 0; m < 128; m++) a += Wn[f * 128 + m] * B[m * 64 + j];
        O[kk] = a;
    } else if (id < 33152) {              // three [128] bias composites
        int k = id - 32768, sel = k >> 7, j = k & 127;
        const float* B = (sel == 0) ? Watt : (sel == 1) ? (Watt + 128 * 128) : Wupd;
        float* O = (sel == 0) ? g_bcu : (sel == 1) ? g_bcv : g_bnu;
        float a = (sel == 0) ? batt1[j] : 0.f;   // fold b_att1 into bcu
        for (int m = 0; m < 128; m++) a += bn[m] * B[m * 128 + j];
        O[j] = a;
    } else if (id < 33280) {              // two [64] head biases
        int k = id - 33152, sel = k >> 6, j = k & 63;
        const float* B = sel ? Wa1 : Wy1;
        float a = sel ? ba1[j] : by1[j];
        for (int m = 0; m < 128; m++) a += bn[m] * B[m * 64 + j];
        (sel ? g_b1a : g_b1y)[j] = a;
    }
}

// ---------------------------------------------------------------------------
// CSR build: histogram, 2-level parallel scan, fill
// ---------------------------------------------------------------------------
__global__ void hist_k(const int* __restrict__ dst, int E) {
    for (int i = blockIdx.x * blockDim.x + threadIdx.x; i < E; i += gridDim.x * blockDim.x)
        atomicAdd(&g_deg[dst[i]], 1);
}

__global__ void scanA_k(int n) {
    __shared__ int wsum[32];
    int t = threadIdx.x, lane = t & 31, wid = t >> 5;
    int i = blockIdx.x * 1024 + t;
    int v = (i < n) ? g_deg[i] : 0;
    int x = v;
#pragma unroll
    for (int o = 1; o < 32; o <<= 1) {
        int y = __shfl_up_sync(0xffffffffu, x, o);
        if (lane >= o) x += y;
    }
    if (lane == 31) wsum[wid] = x;
    __syncthreads();
    if (wid == 0) {
        int w = wsum[lane];
#pragma unroll
        for (int o = 1; o < 32; o <<= 1) {
            int y = __shfl_up_sync(0xffffffffu, w, o);
            if (lane >= o) w += y;
        }
        wsum[lane] = w;
    }
    __syncthreads();
    int excl = (wid ? wsum[wid - 1] : 0) + x - v;
    if (i < n) g_off[i] = excl;
    if (t == 0) g_bsum[blockIdx.x] = wsum[31];
}

// scanB: exclusive scan of nb block sums (nb <= 64), single block
__global__ void scanB_k(int nb) {
    __shared__ int s[64];
    int t = threadIdx.x;
    if (t < nb) s[t] = g_bsum[t];
    __syncthreads();
    if (t == 0) {
        int acc = 0;
        for (int b = 0; b < nb; b++) { int v = s[b]; s[b] = acc; acc += v; }
    }
    __syncthreads();
    if (t < nb) g_bsum[t] = s[t];
}

// addoff: globalize per-block exclusive offsets
__global__ void addoff_k(int n) {
    int i = blockIdx.x * blockDim.x + threadIdx.x;
    if (i < n) g_off[i] += g_bsum[i >> 10];
}

// fill: p = exp(s-max) in place, accumulate g_sum, slot edges into CSR.
// atomicAdd on g_off itself: post-fill, g_off[d] == original g_off[d+1],
// so node d's range is [d ? g_off[d-1] : 0, g_off[d]).
__global__ void fill_k(const int* __restrict__ dst, int E) {
    float mx = fdecode(g_maxkey);
    float loc = 0.f;
    for (int i = blockIdx.x * blockDim.x + threadIdx.x; i < E; i += gridDim.x * blockDim.x) {
        float p = expf(g_s[i] - mx);
        g_s[i] = p;
        loc += p;
        int slot = atomicAdd(&g_off[dst[i]], 1);
        g_eid[slot] = i;
    }
    for (int o = 16; o; o >>= 1) loc += __shfl_xor_sync(0xffffffffu, loc, o);
    __shared__ float ws[8];
    int lane = threadIdx.x & 31, wid = threadIdx.x >> 5;
    if (lane == 0) ws[wid] = loc;
    __syncthreads();
    if (threadIdx.x == 0) {
        float tot = 0.f;
        for (int i = 0; i < (int)(blockDim.x >> 5); i++) tot += ws[i];
        atomicAdd(&g_sum, tot);
    }
}

// ---------------------------------------------------------------------------
// Encoder: u,v [n,128] from mol_x [n,64] via composite weights.
// ---------------------------------------------------------------------------
__global__ void __launch_bounds__(256)
enc_k(const float* __restrict__ X, int n) {
    extern __shared__ float sm[];
    float* Ws = sm;            // 2 * 8192
    float* bs = sm + 16384;    // 2 * 128
    float* Xs = bs + 256;      // 32 * 64
    int t = threadIdx.x;
    int col = t & 127, half = t >> 7;
    for (int i = t; i < 2048; i += 256) ((float4*)Ws)[i]          = ((const float4*)g_Wcu)[i];
    for (int i = t; i < 2048; i += 256) ((float4*)(Ws + 8192))[i] = ((const float4*)g_Wcv)[i];
    if (t < 128) { bs[t] = g_bcu[t]; bs[128 + t] = g_bcv[t]; }

    for (int row0 = blockIdx.x * 32; row0 < n; row0 += gridDim.x * 32) {
        int nr = min(32, n - row0);
        __syncthreads();
        for (int i = t; i < nr * 16; i += 256)
            ((float4*)Xs)[i] = ((const float4*)(X + (size_t)row0 * 64))[i];
        __syncthreads();

#pragma unroll 1
        for (int g = 0; g < 2; g++) {
            const float* Wg = Ws + g * 8192;
            float acc[16];
#pragma unroll
            for (int r = 0; r < 16; r++) acc[r] = 0.f;
            for (int k4 = 0; k4 < 64; k4 += 4) {
                float w0 = Wg[(k4 + 0) * 128 + col];
                float w1 = Wg[(k4 + 1) * 128 + col];
                float w2 = Wg[(k4 + 2) * 128 + col];
                float w3 = Wg[(k4 + 3) * 128 + col];
#pragma unroll
                for (int r = 0; r < 16; r++) {
                    float4 xv = *(const float4*)&Xs[(half * 16 + r) * 64 + k4];
                    acc[r] += xv.x * w0 + xv.y * w1 + xv.z * w2 + xv.w * w3;
                }
            }
            float bv = bs[g * 128 + col];
            float* O = g ? g_v : g_u;
            int rmax = min(16, nr - half * 16);
            for (int r = 0; r < rmax; r++)
                O[(size_t)(row0 + half * 16 + r) * 128 + col] = acc[r] + bv;
        }
    }
}

// ---------------------------------------------------------------------------
// Edge attention score + fused global max (persistent warps, 2-edge ILP,
// lane-split pos gather). b_att1 pre-folded into g_u.
// ---------------------------------------------------------------------------
__global__ void edge_k(const int* __restrict__ src, const int* __restrict__ dst,
                       const float* __restrict__ pos,
                       const float* __restrict__ Wd,
                       const float* __restrict__ W2, const float* __restrict__ b2,
                       int E) {
    int lane = threadIdx.x & 31;
    int wid = threadIdx.x >> 5;
    int gw = (blockIdx.x * blockDim.x + threadIdx.x) >> 5;
    int nw = (gridDim.x * blockDim.x) >> 5;

    float4 c0 = ((const float4*)Wd)[lane];
    float4 c1 = ((const float4*)(Wd + 128))[lane];
    float4 c2 = ((const float4*)(Wd + 256))[lane];
    float4 w2 = ((const float4*)W2)[lane];
    float b2v = b2[0];

    const unsigned FULL = 0xffffffffu;
    float wmax = -FLT_MAX;
    for (int e0 = gw * 2; e0 < E; e0 += 2 * nw) {
        int e1 = e0 + 1;
        bool has1 = e1 < E;                 // warp-uniform
        int e1c = has1 ? e1 : e0;           // clamped index (always valid)

        int sn0 = src[e0], dn0 = dst[e0];
        int sn1 = src[e1c], dn1 = dst[e1c];

        float4 a0 = ((const float4*)(g_u + (size_t)dn0 * 128))[lane];
        float4 j0 = ((const float4*)(g_v + (size_t)sn0 * 128))[lane];
        float4 a1 = ((const float4*)(g_u + (size_t)dn1 * 128))[lane];
        float4 j1 = ((const float4*)(g_v + (size_t)sn1 * 128))[lane];

        float pv = 0.f;
        if (lane < 12) {
            int sel = lane / 3, comp = lane - sel * 3;
            int node = (sel == 0) ? dn0 : (sel == 1) ? sn0 : (sel == 2) ? dn1 : sn1;
            pv = pos[node * 3 + comp];
        }
        float dx0 = __shfl_sync(FULL, pv, 0) - __shfl_sync(FULL, pv, 3);
        float dy0 = __shfl_sync(FULL, pv, 1) - __shfl_sync(FULL, pv, 4);
        float dz0 = __shfl_sync(FULL, pv, 2) - __shfl_sync(FULL, pv, 5);
        float dx1 = __shfl_sync(FULL, pv, 6) - __shfl_sync(FULL, pv, 9);
        float dy1 = __shfl_sync(FULL, pv, 7) - __shfl_sync(FULL, pv, 10);
        float dz1 = __shfl_sync(FULL, pv, 8) - __shfl_sync(FULL, pv, 11);

        float p0, p1;
        {
            float t0 = fmaxf(a0.x + j0.x + dx0 * c0.x + dy0 * c1.x + dz0 * c2.x, 0.f);
            float t1 = fmaxf(a0.y + j0.y + dx0 * c0.y + dy0 * c1.y + dz0 * c2.y, 0.f);
            float t2 = fmaxf(a0.z + j0.z + dx0 * c0.z + dy0 * c1.z + dz0 * c2.z, 0.f);
            float t3 = fmaxf(a0.w + j0.w + dx0 * c0.w + dy0 * c1.w + dz0 * c2.w, 0.f);
            p0 = t0 * w2.x + t1 * w2.y + t2 * w2.z + t3 * w2.w;
        }
        {
            float t0 = fmaxf(a1.x + j1.x + dx1 * c0.x + dy1 * c1.x + dz1 * c2.x, 0.f);
            float t1 = fmaxf(a1.y + j1.y + dx1 * c0.y + dy1 * c1.y + dz1 * c2.y, 0.f);
            float t2 = fmaxf(a1.z + j1.z + dx1 * c0.z + dy1 * c1.z + dz1 * c2.z, 0.f);
            float t3 = fmaxf(a1.w + j1.w + dx1 * c0.w + dy1 * c1.w + dz1 * c2.w, 0.f);
            p1 = t0 * w2.x + t1 * w2.y + t2 * w2.z + t3 * w2.w;
        }

#pragma unroll
        for (int o = 16; o; o >>= 1) {
            p0 += __shfl_xor_sync(FULL, p0, o);
            p1 += __shfl_xor_sync(FULL, p1, o);
        }
        float s0 = p0 + b2v;
        float s1 = p1 + b2v;
        if (lane == 0) g_s[e0] = s0;
        wmax = fmaxf(wmax, s0);
        if (has1) {
            if (lane == 0) g_s[e1] = s1;
            wmax = fmaxf(wmax, s1);
        }
    }

    __shared__ float wm[8];
    if (lane == 0) wm[wid] = wmax;
    __syncthreads();
    if (threadIdx.x == 0) {
        float m = wm[0];
        for (int i = 1; i < (int)(blockDim.x >> 5); i++) m = fmaxf(m, wm[i]);
        atomicMax(&g_maxkey, fkey(m));
    }
}

// ---------------------------------------------------------------------------
// Gather aggregation (atomic-free): HALF-WARP per node, register accumulate.
// 2-edge unroll: both edges' chains issued together for MLP=2 on the
// long-latency eid->s/src->x gather chains.
// ---------------------------------------------------------------------------
__global__ void gather_k(const int* __restrict__ src, const float* __restrict__ molx,
                         int N) {
    int node = (blockIdx.x * blockDim.x + threadIdx.x) >> 4;
    int l16 = threadIdx.x & 15;
    if (node >= N) return;
    int beg = node ? g_off[node - 1] : 0;
    int end = g_off[node];
    float4 acc = make_float4(0.f, 0.f, 0.f, 0.f);
    float sp = 0.f;
    int i = beg;
    for (; i + 2 <= end; i += 2) {
        int e0 = g_eid[i], e1 = g_eid[i + 1];
        float p0 = g_s[e0], p1 = g_s[e1];
        int s0 = src[e0], s1 = src[e1];
        float4 x0 = ((const float4*)(molx + (size_t)s0 * 64))[l16];
        float4 x1 = ((const float4*)(molx + (size_t)s1 * 64))[l16];
        acc.x += x0.x * p0; acc.y += x0.y * p0; acc.z += x0.z * p0; acc.w += x0.w * p0;
        acc.x += x1.x * p1; acc.y += x1.y * p1; acc.z += x1.z * p1; acc.w += x1.w * p1;
        sp += p0 + p1;
    }
    if (i < end) {
        int e = g_eid[i];
        float p = g_s[e];
        int sn = src[e];
        float4 x = ((const float4*)(molx + (size_t)sn * 64))[l16];
        acc.x += x.x * p; acc.y += x.y * p; acc.z += x.z * p; acc.w += x.w * p;
        sp += p;
    }
    ((float4*)(g_aggr64 + (size_t)node * 64))[l16] = acc;
    if (l16 == 0) g_sp[node] = sp;
}

// ---------------------------------------------------------------------------
// Final GEMM (K=64): mol_feats = (aggr64@Wnu + sp*bnu)/sum + b_upd
// ---------------------------------------------------------------------------
__global__ void __launch_bounds__(256)
final_k(const float* __restrict__ bupd, float* __restrict__ Y, int n) {
    extern __shared__ float sm[];
    float* Ws = sm;            // 8192
    float* bs = sm + 8192;     // 2*128 (bnu, bupd)
    float* Xs = bs + 256;      // 32*64
    int t = threadIdx.x;
    int col = t & 127, half = t >> 7;
    for (int i = t; i < 2048; i += 256) ((float4*)Ws)[i] = ((const float4*)g_Wnu)[i];
    if (t < 128) { bs[t] = g_bnu[t]; bs[128 + t] = bupd[t]; }

    float is = 1.f / g_sum;

    for (int row0 = blockIdx.x * 32; row0 < n; row0 += gridDim.x * 32) {
        int nr = min(32, n - row0);
        __syncthreads();
        for (int i = t; i < nr * 16; i += 256)
            ((float4*)Xs)[i] = ((const float4*)(g_aggr64 + (size_t)row0 * 64))[i];
        __syncthreads();

        float acc[16];
#pragma unroll
        for (int r = 0; r < 16; r++) acc[r] = 0.f;
        for (int k4 = 0; k4 < 64; k4 += 4) {
            float w0 = Ws[(k4 + 0) * 128 + col];
            float w1 = Ws[(k4 + 1) * 128 + col];
            float w2 = Ws[(k4 + 2) * 128 + col];
            float w3 = Ws[(k4 + 3) * 128 + col];
#pragma unroll
            for (int r = 0; r < 16; r++) {
                float4 xv = *(const float4*)&Xs[(half * 16 + r) * 64 + k4];
                acc[r] += xv.x * w0 + xv.y * w1 + xv.z * w2 + xv.w * w3;
            }
        }
        float bnuv = bs[col], bupv = bs[128 + col];
        int rmax = min(16, nr - half * 16);
        for (int r = 0; r < rmax; r++) {
            int row = row0 + half * 16 + r;
            float sp = g_sp[row];
            Y[(size_t)row * 128 + col] = (acc[r] + sp * bnuv) * is + bupv;
        }
    }
}

// ---------------------------------------------------------------------------
// BOTH heads in one launch. Block picks (y) or (a) params by blockIdx.
// ---------------------------------------------------------------------------
__global__ void heads_k(const float* __restrict__ Ry, const float* __restrict__ W2y,
                        const float* __restrict__ b2y, float* __restrict__ outY, int nY,
                        const float* __restrict__ Ra, const float* __restrict__ W2a,
                        const float* __restrict__ b2a, float* __restrict__ outA, int nA,
                        int blocksY) {
    __shared__ float W1s[64 * 64];
    __shared__ float b1s[64];
    __shared__ float W2s[64];
    __shared__ float rows[8][64];
    int t = threadIdx.x, lane = t & 31, wid = t >> 5;

    bool isY = blockIdx.x < blocksY;
    int bid = isY ? blockIdx.x : blockIdx.x - blocksY;
    const float* R   = isY ? Ry : Ra;
    const float* W1c = isY ? g_W1y : g_W1a;
    const float* b1c = isY ? g_b1y : g_b1a;
    const float* W2  = isY ? W2y : W2a;
    const float* b2  = isY ? b2y : b2a;
    float* out = isY ? outY : outA;
    int n = isY ? nY : nA;

    for (int i = t; i < 64 * 64; i += 256) W1s[i] = W1c[i];
    if (t < 64) { b1s[t] = b1c[t]; W2s[t] = W2[t]; }
    __syncthreads();
    float b2v = b2[0];
    int row = bid * 8 + wid;
    if (row < n) {
        if (lane < 16) ((float4*)rows[wid])[lane] = ((const float4*)(R + (size_t)row * 64))[lane];
        __syncwarp();
        float h0 = b1s[lane], h1 = b1s[lane + 32];
#pragma unroll 8
        for (int k = 0; k < 64; k++) {
            float x = rows[wid][k];
            h0 += x * W1s[k * 64 + lane];
            h1 += x * W1s[k * 64 + lane + 32];
        }
        float p = fmaxf(h0, 0.f) * W2s[lane] + fmaxf(h1, 0.f) * W2s[lane + 32];
        for (int o = 16; o; o >>= 1) p += __shfl_xor_sync(0xffffffffu, p, o);
        if (lane == 0) out[row] = p + b2v;
    }
}

// ---------------------------------------------------------------------------
extern "C" void kernel_launch(void* const* d_in, const int* in_sizes, int n_in,
                              void* d_out, int out_size) {
    const float* mol_x  = (const float*)d_in[0];
    const float* pos    = (const float*)d_in[1];
    const float* rx     = (const float*)d_in[2];
    const float* tx     = (const float*)d_in[3];
    const int*   ei     = (const int*)d_in[4];
    const float* W_node = (const float*)d_in[5];
    const float* b_node = (const float*)d_in[6];
    const float* W_att1 = (const float*)d_in[7];
    const float* b_att1 = (const float*)d_in[8];
    const float* W_att2 = (const float*)d_in[9];
    const float* b_att2 = (const float*)d_in[10];
    const float* W_upd  = (const float*)d_in[11];
    const float* b_upd  = (const float*)d_in[12];
    const float* Wy1 = (const float*)d_in[13];
    const float* by1 = (const float*)d_in[14];
    const float* Wy2 = (const float*)d_in[15];
    const float* by2 = (const float*)d_in[16];
    const float* Wa1 = (const float*)d_in[17];
    const float* ba1 = (const float*)d_in[18];
    const float* Wa2 = (const float*)d_in[19];
    const float* ba2 = (const float*)d_in[20];

    int N  = in_sizes[0] / 64;
    int NR = in_sizes[2] / 64;
    int NT = in_sizes[3] / 64;
    int E  = in_sizes[4] / 2;
    const int* srcP = ei;
    const int* dstP = ei + E;

    float* out   = (float*)d_out;
    float* out_y = out;             // pred_yield  [NR]
    float* out_a = out + NR;        // pred_activity [NT]
    float* out_m = out + NR + NT;   // mol_feats [N,128]

    int smem_enc   = (2 * 64 * 128 + 2 * 128 + 32 * 64) * 4;  // ~74 KB
    int smem_final = (64 * 128 + 2 * 128 + 32 * 64) * 4;      // ~42 KB
    cudaFuncSetAttribute(enc_k,   cudaFuncAttributeMaxDynamicSharedMemorySize, smem_enc);
    cudaFuncSetAttribute(final_k, cudaFuncAttributeMaxDynamicSharedMemorySize, smem_final);

    auto pgrid = [](int rows, int cap) {
        int tiles = (rows + 31) / 32;
        return tiles < cap ? tiles : cap;
    };

    init_k<<<64, 256>>>(N);
    compose_all_k<<<130, 256>>>(W_node, b_node, W_att1, b_att1, W_upd,
                                Wy1, by1, Wa1, ba1);

    // CSR: histogram + 2-level parallel scan
    int nbScan = (N + 1023) / 1024;
    hist_k<<<592, 256>>>(dstP, E);
    scanA_k<<<nbScan, 1024>>>(N);
    scanB_k<<<1, 64>>>(nbScan);
    addoff_k<<<(N + 255) / 256, 256>>>(N);

    // u, v from mol_x via composite weights
    enc_k<<<pgrid(N, 2 * 148), 256, smem_enc>>>(mol_x, N);

    // per-edge score + fused global max
    edge_k<<<592, 256>>>(srcP, dstP, pos, W_att1 + 256 * 128, W_att2, b_att2, E);

    // exp + g_sum + CSR fill
    fill_k<<<592, 256>>>(dstP, E);

    // atomic-free gather aggregation (also produces g_sp), 2-edge ILP
    gather_k<<<(N * 16 + 255) / 256, 256>>>(srcP, mol_x, N);

    // final K=64 GEMM -> mol_feats
    final_k<<<pgrid(N, 4 * 148), 256, smem_final>>>(b_upd, out_m, N);

    // both heads in one launch
    int blocksY = (NR + 7) / 8, blocksA = (NT + 7) / 8;
    heads_k<<<blocksY + blocksA, 256>>>(rx, Wy2, by2, out_y, NR,
                                        tx, Wa2, ba2, out_a, NT, blocksY);
}

// round 16
// speedup vs baseline: 1.1046x; 1.0112x over previous
#include <cuda_runtime.h>
#include <math.h>
#include <float.h>

#define NMAX 50000
#define EMAX 400000

// Scratch (allocation-free rule: __device__ globals)
__device__ float g_u[NMAX * 128];
__device__ float g_v[NMAX * 128];
__device__ float g_aggr64[NMAX * 64];   // aggregated mol_x (64-wide)
__device__ float g_sp[NMAX];            // per-node sum of p
__device__ float g_s[EMAX];             // edge scores, then p=exp(s-max)
__device__ int   g_eid[EMAX];           // CSR edge ids
__device__ int   g_deg[NMAX];           // degree histogram
__device__ int   g_off[NMAX + 1];       // CSR offsets (mutated by fill)
__device__ int   g_bsum[64];            // scan block sums (raw totals)
__device__ unsigned int g_maxkey;
__device__ float g_sum;
// composite weights
__device__ float g_Wcu[64 * 128], g_Wcv[64 * 128], g_Wnu[64 * 128];
__device__ float g_bcu[128], g_bcv[128], g_bnu[128];
__device__ float g_W1y[64 * 64], g_b1y[64];
__device__ float g_W1a[64 * 64], g_b1a[64];

// --- monotonic float<->uint key for atomicMax over signed floats ---
__device__ __forceinline__ unsigned fkey(float f) {
    unsigned b = __float_as_uint(f);
    return (b & 0x80000000u) ? ~b : (b | 0x80000000u);
}
__device__ __forceinline__ float fdecode(unsigned k) {
    return __uint_as_float((k & 0x80000000u) ? (k ^ 0x80000000u) : ~k);
}

// ---------------------------------------------------------------------------
// ONE kernel: all composite weights + softmax-scalar reset + g_deg zeroing.
// g_bcu folds in b_att1.
// ---------------------------------------------------------------------------
__global__ void compose_all_k(const float* __restrict__ Wn, const float* __restrict__ bn,
                              const float* __restrict__ Watt, const float* __restrict__ batt1,
                              const float* __restrict__ Wupd,
                              const float* __restrict__ Wy1, const float* __restrict__ by1,
                              const float* __restrict__ Wa1, const float* __restrict__ ba1,
                              int N) {
    int id = blockIdx.x * blockDim.x + threadIdx.x;
    if (id < 24576) {                     // three [64,128] composites
        int sel = id >> 13, k = id & 8191, f = k >> 7, j = k & 127;
        const float* B = (sel == 0) ? Watt : (sel == 1) ? (Watt + 128 * 128) : Wupd;
        float* O = (sel == 0) ? g_Wcu : (sel == 1) ? g_Wcv : g_Wnu;
        float a = 0.f;
        for (int m = 0; m < 128; m++) a += Wn[f * 128 + m] * B[m * 128 + j];
        O[k] = a;
    } else if (id < 32768) {              // two [64,64] head composites
        int k = id - 24576, sel = k >> 12, kk = k & 4095, f = kk >> 6, j = kk & 63;
        const float* B = sel ? Wa1 : Wy1;
        float* O = sel ? g_W1a : g_W1y;
        float a = 0.f;
        for (int m = 0; m < 128; m++) a += Wn[f * 128 + m] * B[m * 64 + j];
        O[kk] = a;
    } else if (id < 33152) {              // three [128] bias composites
        int k = id - 32768, sel = k >> 7, j = k & 127;
        const float* B = (sel == 0) ? Watt : (sel == 1) ? (Watt + 128 * 128) : Wupd;
        float* O = (sel == 0) ? g_bcu : (sel == 1) ? g_bcv : g_bnu;
        float a = (sel == 0) ? batt1[j] : 0.f;   // fold b_att1 into bcu
        for (int m = 0; m < 128; m++) a += bn[m] * B[m * 128 + j];
        O[j] = a;
    } else if (id < 33280) {              // two [64] head biases
        int k = id - 33152, sel = k >> 6, j = k & 63;
        const float* B = sel ? Wa1 : Wy1;
        float a = sel ? ba1[j] : by1[j];
        for (int m = 0; m < 128; m++) a += bn[m] * B[m * 64 + j];
        (sel ? g_b1a : g_b1y)[j] = a;
    } else if (id == 33280) {             // softmax scalar reset
        g_maxkey = 0u;
        g_sum = 0.f;
    } else if (id >= 33281 && id < 33281 + N) {  // degree histogram zero
        g_deg[id - 33281] = 0;
    }
}

// ---------------------------------------------------------------------------
// CSR build: histogram, scanA, addoff (scanB merged: in-smem prefix)
// ---------------------------------------------------------------------------
__global__ void hist_k(const int* __restrict__ dst, int E) {
    for (int i = blockIdx.x * blockDim.x + threadIdx.x; i < E; i += gridDim.x * blockDim.x)
        atomicAdd(&g_deg[dst[i]], 1);
}

__global__ void scanA_k(int n) {
    __shared__ int wsum[32];
    int t = threadIdx.x, lane = t & 31, wid = t >> 5;
    int i = blockIdx.x * 1024 + t;
    int v = (i < n) ? g_deg[i] : 0;
    int x = v;
#pragma unroll
    for (int o = 1; o < 32; o <<= 1) {
        int y = __shfl_up_sync(0xffffffffu, x, o);
        if (lane >= o) x += y;
    }
    if (lane == 31) wsum[wid] = x;
    __syncthreads();
    if (wid == 0) {
        int w = wsum[lane];
#pragma unroll
        for (int o = 1; o < 32; o <<= 1) {
            int y = __shfl_up_sync(0xffffffffu, w, o);
            if (lane >= o) w += y;
        }
        wsum[lane] = w;
    }
    __syncthreads();
    int excl = (wid ? wsum[wid - 1] : 0) + x - v;
    if (i < n) g_off[i] = excl;
    if (t == 0) g_bsum[blockIdx.x] = wsum[31];
}

// addoff: stage block sums in smem ONCE, prefix in-smem (thread 0), then add.
__global__ void addoff_k(int n, int nb) {
    __shared__ int pre[64];
    int t = threadIdx.x;
    if (t < nb) pre[t] = g_bsum[t];
    __syncthreads();
    if (t == 0) {
        int acc = 0;
        for (int b = 0; b < nb; b++) { int v = pre[b]; pre[b] = acc; acc += v; }
    }
    __syncthreads();
    int i = blockIdx.x * blockDim.x + t;
    if (i < n) g_off[i] += pre[i >> 10];
}

// fill: p = exp(s-max) in place, accumulate g_sum, slot edges into CSR.
// atomicAdd on g_off itself: post-fill, g_off[d] == original g_off[d+1],
// so node d's range is [d ? g_off[d-1] : 0, g_off[d]).
__global__ void fill_k(const int* __restrict__ dst, int E) {
    float mx = fdecode(g_maxkey);
    float loc = 0.f;
    for (int i = blockIdx.x * blockDim.x + threadIdx.x; i < E; i += gridDim.x * blockDim.x) {
        float p = expf(g_s[i] - mx);
        g_s[i] = p;
        loc += p;
        int slot = atomicAdd(&g_off[dst[i]], 1);
        g_eid[slot] = i;
    }
    for (int o = 16; o; o >>= 1) loc += __shfl_xor_sync(0xffffffffu, loc, o);
    __shared__ float ws[8];
    int lane = threadIdx.x & 31, wid = threadIdx.x >> 5;
    if (lane == 0) ws[wid] = loc;
    __syncthreads();
    if (threadIdx.x == 0) {
        float tot = 0.f;
        for (int i = 0; i < (int)(blockDim.x >> 5); i++) tot += ws[i];
        atomicAdd(&g_sum, tot);
    }
}

// ---------------------------------------------------------------------------
// Encoder: u,v [n,128] from mol_x [n,64] via composite weights.
// ---------------------------------------------------------------------------
__global__ void __launch_bounds__(256)
enc_k(const float* __restrict__ X, int n) {
    extern __shared__ float sm[];
    float* Ws = sm;            // 2 * 8192
    float* bs = sm + 16384;    // 2 * 128
    float* Xs = bs + 256;      // 32 * 64
    int t = threadIdx.x;
    int col = t & 127, half = t >> 7;
    for (int i = t; i < 2048; i += 256) ((float4*)Ws)[i]          = ((const float4*)g_Wcu)[i];
    for (int i = t; i < 2048; i += 256) ((float4*)(Ws + 8192))[i] = ((const float4*)g_Wcv)[i];
    if (t < 128) { bs[t] = g_bcu[t]; bs[128 + t] = g_bcv[t]; }

    for (int row0 = blockIdx.x * 32; row0 < n; row0 += gridDim.x * 32) {
        int nr = min(32, n - row0);
        __syncthreads();
        for (int i = t; i < nr * 16; i += 256)
            ((float4*)Xs)[i] = ((const float4*)(X + (size_t)row0 * 64))[i];
        __syncthreads();

#pragma unroll 1
        for (int g = 0; g < 2; g++) {
            const float* Wg = Ws + g * 8192;
            float acc[16];
#pragma unroll
            for (int r = 0; r < 16; r++) acc[r] = 0.f;
            for (int k4 = 0; k4 < 64; k4 += 4) {
                float w0 = Wg[(k4 + 0) * 128 + col];
                float w1 = Wg[(k4 + 1) * 128 + col];
                float w2 = Wg[(k4 + 2) * 128 + col];
                float w3 = Wg[(k4 + 3) * 128 + col];
#pragma unroll
                for (int r = 0; r < 16; r++) {
                    float4 xv = *(const float4*)&Xs[(half * 16 + r) * 64 + k4];
                    acc[r] += xv.x * w0 + xv.y * w1 + xv.z * w2 + xv.w * w3;
                }
            }
            float bv = bs[g * 128 + col];
            float* O = g ? g_v : g_u;
            int rmax = min(16, nr - half * 16);
            for (int r = 0; r < rmax; r++)
                O[(size_t)(row0 + half * 16 + r) * 128 + col] = acc[r] + bv;
        }
    }
}

// ---------------------------------------------------------------------------
// Edge attention score + fused global max (persistent warps, 2-edge ILP,
// lane-split pos gather, interleaved SHFL butterflies). b_att1 pre-folded
// into g_u.
// ---------------------------------------------------------------------------
__global__ void edge_k(const int* __restrict__ src, const int* __restrict__ dst,
                       const float* __restrict__ pos,
                       const float* __restrict__ Wd,
                       const float* __restrict__ W2, const float* __restrict__ b2,
                       int E) {
    int lane = threadIdx.x & 31;
    int wid = threadIdx.x >> 5;
    int gw = (blockIdx.x * blockDim.x + threadIdx.x) >> 5;
    int nw = (gridDim.x * blockDim.x) >> 5;

    float4 c0 = ((const float4*)Wd)[lane];
    float4 c1 = ((const float4*)(Wd + 128))[lane];
    float4 c2 = ((const float4*)(Wd + 256))[lane];
    float4 w2 = ((const float4*)W2)[lane];
    float b2v = b2[0];

    const unsigned FULL = 0xffffffffu;
    float wmax = -FLT_MAX;
    for (int e0 = gw * 2; e0 < E; e0 += 2 * nw) {
        int e1 = e0 + 1;
        bool has1 = e1 < E;                 // warp-uniform
        int e1c = has1 ? e1 : e0;           // clamped index (always valid)

        int sn0 = src[e0], dn0 = dst[e0];
        int sn1 = src[e1c], dn1 = dst[e1c];

        float4 a0 = ((const float4*)(g_u + (size_t)dn0 * 128))[lane];
        float4 j0 = ((const float4*)(g_v + (size_t)sn0 * 128))[lane];
        float4 a1 = ((const float4*)(g_u + (size_t)dn1 * 128))[lane];
        float4 j1 = ((const float4*)(g_v + (size_t)sn1 * 128))[lane];

        float pv = 0.f;
        if (lane < 12) {
            int sel = lane / 3, comp = lane - sel * 3;
            int node = (sel == 0) ? dn0 : (sel == 1) ? sn0 : (sel == 2) ? dn1 : sn1;
            pv = pos[node * 3 + comp];
        }
        float dx0 = __shfl_sync(FULL, pv, 0) - __shfl_sync(FULL, pv, 3);
        float dy0 = __shfl_sync(FULL, pv, 1) - __shfl_sync(FULL, pv, 4);
        float dz0 = __shfl_sync(FULL, pv, 2) - __shfl_sync(FULL, pv, 5);
        float dx1 = __shfl_sync(FULL, pv, 6) - __shfl_sync(FULL, pv, 9);
        float dy1 = __shfl_sync(FULL, pv, 7) - __shfl_sync(FULL, pv, 10);
        float dz1 = __shfl_sync(FULL, pv, 8) - __shfl_sync(FULL, pv, 11);

        float p0, p1;
        {
            float t0 = fmaxf(a0.x + j0.x + dx0 * c0.x + dy0 * c1.x + dz0 * c2.x, 0.f);
            float t1 = fmaxf(a0.y + j0.y + dx0 * c0.y + dy0 * c1.y + dz0 * c2.y, 0.f);
            float t2 = fmaxf(a0.z + j0.z + dx0 * c0.z + dy0 * c1.z + dz0 * c2.z, 0.f);
            float t3 = fmaxf(a0.w + j0.w + dx0 * c0.w + dy0 * c1.w + dz0 * c2.w, 0.f);
            p0 = t0 * w2.x + t1 * w2.y + t2 * w2.z + t3 * w2.w;
        }
        {
            float t0 = fmaxf(a1.x + j1.x + dx1 * c0.x + dy1 * c1.x + dz1 * c2.x, 0.f);
            float t1 = fmaxf(a1.y + j1.y + dx1 * c0.y + dy1 * c1.y + dz1 * c2.y, 0.f);
            float t2 = fmaxf(a1.z + j1.z + dx1 * c0.z + dy1 * c1.z + dz1 * c2.z, 0.f);
            float t3 = fmaxf(a1.w + j1.w + dx1 * c0.w + dy1 * c1.w + dz1 * c2.w, 0.f);
            p1 = t0 * w2.x + t1 * w2.y + t2 * w2.z + t3 * w2.w;
        }

        // interleaved independent shuffle chains
#pragma unroll
        for (int o = 16; o; o >>= 1) {
            p0 += __shfl_xor_sync(FULL, p0, o);
            p1 += __shfl_xor_sync(FULL, p1, o);
        }
        float s0 = p0 + b2v;
        float s1 = p1 + b2v;
        if (lane == 0) g_s[e0] = s0;
        wmax = fmaxf(wmax, s0);
        if (has1) {
            if (lane == 0) g_s[e1] = s1;
            wmax = fmaxf(wmax, s1);
        }
    }

    __shared__ float wm[8];
    if (lane == 0) wm[wid] = wmax;
    __syncthreads();
    if (threadIdx.x == 0) {
        float m = wm[0];
        for (int i = 1; i < (int)(blockDim.x >> 5); i++) m = fmaxf(m, wm[i]);
        atomicMax(&g_maxkey, fkey(m));
    }
}

// ---------------------------------------------------------------------------
// Gather aggregation (atomic-free): HALF-WARP per node, 2-edge ILP.
// ---------------------------------------------------------------------------
__global__ void gather_k(const int* __restrict__ src, const float* __restrict__ molx,
                         int N) {
    int node = (blockIdx.x * blockDim.x + threadIdx.x) >> 4;
    int l16 = threadIdx.x & 15;
    if (node >= N) return;
    int beg = node ? g_off[node - 1] : 0;
    int end = g_off[node];
    float4 acc = make_float4(0.f, 0.f, 0.f, 0.f);
    float sp = 0.f;
    int i = beg;
    for (; i + 2 <= end; i += 2) {
        int e0 = g_eid[i], e1 = g_eid[i + 1];
        float p0 = g_s[e0], p1 = g_s[e1];
        int s0 = src[e0], s1 = src[e1];
        float4 x0 = ((const float4*)(molx + (size_t)s0 * 64))[l16];
        float4 x1 = ((const float4*)(molx + (size_t)s1 * 64))[l16];
        acc.x += x0.x * p0; acc.y += x0.y * p0; acc.z += x0.z * p0; acc.w += x0.w * p0;
        acc.x += x1.x * p1; acc.y += x1.y * p1; acc.z += x1.z * p1; acc.w += x1.w * p1;
        sp += p0 + p1;
    }
    if (i < end) {
        int e = g_eid[i];
        float p = g_s[e];
        int sn = src[e];
        float4 x = ((const float4*)(molx + (size_t)sn * 64))[l16];
        acc.x += x.x * p; acc.y += x.y * p; acc.z += x.z * p; acc.w += x.w * p;
        sp += p;
    }
    ((float4*)(g_aggr64 + (size_t)node * 64))[l16] = acc;
    if (l16 == 0) g_sp[node] = sp;
}

// ---------------------------------------------------------------------------
// Final GEMM (K=64): mol_feats = (aggr64@Wnu + sp*bnu)/sum + b_upd
// ---------------------------------------------------------------------------
__global__ void __launch_bounds__(256)
final_k(const float* __restrict__ bupd, float* __restrict__ Y, int n) {
    extern __shared__ float sm[];
    float* Ws = sm;            // 8192
    float* bs = sm + 8192;     // 2*128 (bnu, bupd)
    float* Xs = bs + 256;      // 32*64
    int t = threadIdx.x;
    int col = t & 127, half = t >> 7;
    for (int i = t; i < 2048; i += 256) ((float4*)Ws)[i] = ((const float4*)g_Wnu)[i];
    if (t < 128) { bs[t] = g_bnu[t]; bs[128 + t] = bupd[t]; }

    float is = 1.f / g_sum;

    for (int row0 = blockIdx.x * 32; row0 < n; row0 += gridDim.x * 32) {
        int nr = min(32, n - row0);
        __syncthreads();
        for (int i = t; i < nr * 16; i += 256)
            ((float4*)Xs)[i] = ((const float4*)(g_aggr64 + (size_t)row0 * 64))[i];
        __syncthreads();

        float acc[16];
#pragma unroll
        for (int r = 0; r < 16; r++) acc[r] = 0.f;
        for (int k4 = 0; k4 < 64; k4 += 4) {
            float w0 = Ws[(k4 + 0) * 128 + col];
            float w1 = Ws[(k4 + 1) * 128 + col];
            float w2 = Ws[(k4 + 2) * 128 + col];
            float w3 = Ws[(k4 + 3) * 128 + col];
#pragma unroll
            for (int r = 0; r < 16; r++) {
                float4 xv = *(const float4*)&Xs[(half * 16 + r) * 64 + k4];
                acc[r] += xv.x * w0 + xv.y * w1 + xv.z * w2 + xv.w * w3;
            }
        }
        float bnuv = bs[col], bupv = bs[128 + col];
        int rmax = min(16, nr - half * 16);
        for (int r = 0; r < rmax; r++) {
            int row = row0 + half * 16 + r;
            float sp = g_sp[row];
            Y[(size_t)row * 128 + col] = (acc[r] + sp * bnuv) * is + bupv;
        }
    }
}

// ---------------------------------------------------------------------------
// BOTH heads in one launch. Block picks (y) or (a) params by blockIdx.
// ---------------------------------------------------------------------------
__global__ void heads_k(const float* __restrict__ Ry, const float* __restrict__ W2y,
                        const float* __restrict__ b2y, float* __restrict__ outY, int nY,
                        const float* __restrict__ Ra, const float* __restrict__ W2a,
                        const float* __restrict__ b2a, float* __restrict__ outA, int nA,
                        int blocksY) {
    __shared__ float W1s[64 * 64];
    __shared__ float b1s[64];
    __shared__ float W2s[64];
    __shared__ float rows[8][64];
    int t = threadIdx.x, lane = t & 31, wid = t >> 5;

    bool isY = blockIdx.x < blocksY;
    int bid = isY ? blockIdx.x : blockIdx.x - blocksY;
    const float* R   = isY ? Ry : Ra;
    const float* W1c = isY ? g_W1y : g_W1a;
    const float* b1c = isY ? g_b1y : g_b1a;
    const float* W2  = isY ? W2y : W2a;
    const float* b2  = isY ? b2y : b2a;
    float* out = isY ? outY : outA;
    int n = isY ? nY : nA;

    for (int i = t; i < 64 * 64; i += 256) W1s[i] = W1c[i];
    if (t < 64) { b1s[t] = b1c[t]; W2s[t] = W2[t]; }
    __syncthreads();
    float b2v = b2[0];
    int row = bid * 8 + wid;
    if (row < n) {
        if (lane < 16) ((float4*)rows[wid])[lane] = ((const float4*)(R + (size_t)row * 64))[lane];
        __syncwarp();
        float h0 = b1s[lane], h1 = b1s[lane + 32];
#pragma unroll 8
        for (int k = 0; k < 64; k++) {
            float x = rows[wid][k];
            h0 += x * W1s[k * 64 + lane];
            h1 += x * W1s[k * 64 + lane + 32];
        }
        float p = fmaxf(h0, 0.f) * W2s[lane] + fmaxf(h1, 0.f) * W2s[lane + 32];
        for (int o = 16; o; o >>= 1) p += __shfl_xor_sync(0xffffffffu, p, o);
        if (lane == 0) out[row] = p + b2v;
    }
}

// ---------------------------------------------------------------------------
extern "C" void kernel_launch(void* const* d_in, const int* in_sizes, int n_in,
                              void* d_out, int out_size) {
    const float* mol_x  = (const float*)d_in[0];
    const float* pos    = (const float*)d_in[1];
    const float* rx     = (const float*)d_in[2];
    const float* tx     = (const float*)d_in[3];
    const int*   ei     = (const int*)d_in[4];
    const float* W_node = (const float*)d_in[5];
    const float* b_node = (const float*)d_in[6];
    const float* W_att1 = (const float*)d_in[7];
    const float* b_att1 = (const float*)d_in[8];
    const float* W_att2 = (const float*)d_in[9];
    const float* b_att2 = (const float*)d_in[10];
    const float* W_upd  = (const float*)d_in[11];
    const float* b_upd  = (const float*)d_in[12];
    const float* Wy1 = (const float*)d_in[13];
    const float* by1 = (const float*)d_in[14];
    const float* Wy2 = (const float*)d_in[15];
    const float* by2 = (const float*)d_in[16];
    const float* Wa1 = (const float*)d_in[17];
    const float* ba1 = (const float*)d_in[18];
    const float* Wa2 = (const float*)d_in[19];
    const float* ba2 = (const float*)d_in[20];

    int N  = in_sizes[0] / 64;
    int NR = in_sizes[2] / 64;
    int NT = in_sizes[3] / 64;
    int E  = in_sizes[4] / 2;
    const int* srcP = ei;
    const int* dstP = ei + E;

    float* out   = (float*)d_out;
    float* out_y = out;             // pred_yield  [NR]
    float* out_a = out + NR;        // pred_activity [NT]
    float* out_m = out + NR + NT;   // mol_feats [N,128]

    int smem_enc   = (2 * 64 * 128 + 2 * 128 + 32 * 64) * 4;  // ~74 KB
    int smem_final = (64 * 128 + 2 * 128 + 32 * 64) * 4;      // ~42 KB
    cudaFuncSetAttribute(enc_k,   cudaFuncAttributeMaxDynamicSharedMemorySize, smem_enc);
    cudaFuncSetAttribute(final_k, cudaFuncAttributeMaxDynamicSharedMemorySize, smem_final);

    auto pgrid = [](int rows, int cap) {
        int tiles = (rows + 31) / 32;
        return tiles < cap ? tiles : cap;
    };

    // composite weights + scalar reset + deg zeroing, one launch
    int composeBlocks = (33281 + N + 255) / 256;
    compose_all_k<<<composeBlocks, 256>>>(W_node, b_node, W_att1, b_att1, W_upd,
                                          Wy1, by1, Wa1, ba1, N);

    // CSR: histogram + scan (scanB merged into addoff)
    int nbScan = (N + 1023) / 1024;
    hist_k<<<592, 256>>>(dstP, E);
    scanA_k<<<nbScan, 1024>>>(N);
    addoff_k<<<(N + 255) / 256, 256>>>(N, nbScan);

    // u, v from mol_x via composite weights
    enc_k<<<pgrid(N, 2 * 148), 256, smem_enc>>>(mol_x, N);

    // per-edge score + fused global max
    edge_k<<<592, 256>>>(srcP, dstP, pos, W_att1 + 256 * 128, W_att2, b_att2, E);

    // exp + g_sum + CSR fill
    fill_k<<<592, 256>>>(dstP, E);

    // atomic-free gather aggregation (also produces g_sp)
    gather_k<<<(N * 16 + 255) / 256, 256>>>(srcP, mol_x, N);

    // final K=64 GEMM -> mol_feats
    final_k<<<pgrid(N, 4 * 148), 256, smem_final>>>(b_upd, out_m, N);

    // both heads in one launch
    int blocksY = (NR + 7) / 8, blocksA = (NT + 7) / 8;
    heads_k<<<blocksY + blocksA, 256>>>(rx, Wy2, by2, out_y, NR,
                                        tx, Wa2, ba2, out_a, NT, blocksY);
}